// round 14
// baseline (speedup 1.0000x reference)
#include <cuda_runtime.h>

// out[b,i,n] = sum_j w[i,j] * x[b,j,n]
// x: [256, 3, 65536] fp32, w: [3,3] fp32, out: [256, 3, 65536] fp32
//
// CONVERGED at the chip's path-independent LTS/L2 fabric ceiling:
// 402.6 MB compulsory traffic / ~6.34 TB/s sustained => ~63.5us period.
// 10 variants tested; all viable configs cluster at 63.5-64.3us (noise
// band +-0.5us). Rejected by measurement: VPT=2/4 batching, .cs/.cg
// hints, L2 evict_last cross-replay residency (x2), persistent
// grid-stride (-17%).
//
// Final config: 1 float4/thread (3x front-batched LDG.128), default-policy
// loads, write-through stores, TPB=128 x 32768 blocks (last unsampled
// geometry cell; maximal CTA coverage of L1tex queues).

static constexpr int N_COLS   = 65536;
static constexpr int N4       = N_COLS / 4;        // 16384 float4 per row
static constexpr int BATCH    = 256;
static constexpr long TOTAL4  = (long)BATCH * N4;  // 4,194,304 threads
static constexpr int TPB      = 128;

__global__ __launch_bounds__(TPB) void rot3_kernel_v8(
    const float4* __restrict__ x,
    const float*  __restrict__ w,
    float4* __restrict__ out)
{
    long idx = (long)blockIdx.x * TPB + threadIdx.x;
    if (idx >= TOTAL4) return;

    int b = (int)(idx >> 14);        // idx / N4
    int n = (int)(idx & (N4 - 1));   // idx % N4

    // Broadcast weight loads — L1-resident after first warp.
    float w00 = __ldg(w + 0), w01 = __ldg(w + 1), w02 = __ldg(w + 2);
    float w10 = __ldg(w + 3), w11 = __ldg(w + 4), w12 = __ldg(w + 5);
    float w20 = __ldg(w + 6), w21 = __ldg(w + 7), w22 = __ldg(w + 8);

    const float4* xb = x + (size_t)b * 3 * N4;
    float4 x0 = __ldg(xb + n);
    float4 x1 = __ldg(xb + N4 + n);
    float4 x2 = __ldg(xb + 2 * N4 + n);

    float4 o0, o1, o2;
    o0.x = w00 * x0.x + w01 * x1.x + w02 * x2.x;
    o0.y = w00 * x0.y + w01 * x1.y + w02 * x2.y;
    o0.z = w00 * x0.z + w01 * x1.z + w02 * x2.z;
    o0.w = w00 * x0.w + w01 * x1.w + w02 * x2.w;

    o1.x = w10 * x0.x + w11 * x1.x + w12 * x2.x;
    o1.y = w10 * x0.y + w11 * x1.y + w12 * x2.y;
    o1.z = w10 * x0.z + w11 * x1.z + w12 * x2.z;
    o1.w = w10 * x0.w + w11 * x1.w + w12 * x2.w;

    o2.x = w20 * x0.x + w21 * x1.x + w22 * x2.x;
    o2.y = w20 * x0.y + w21 * x1.y + w22 * x2.y;
    o2.z = w20 * x0.z + w21 * x1.z + w22 * x2.z;
    o2.w = w20 * x0.w + w21 * x1.w + w22 * x2.w;

    float4* ob = out + (size_t)b * 3 * N4;
    __stwt(ob + n,          o0);
    __stwt(ob + N4 + n,     o1);
    __stwt(ob + 2 * N4 + n, o2);
}

extern "C" void kernel_launch(void* const* d_in, const int* in_sizes, int n_in,
                              void* d_out, int out_size)
{
    const float4* x = (const float4*)d_in[0];
    const float*  w = (const float*)d_in[1];
    float4* out = (float4*)d_out;

    const long blocks = (TOTAL4 + TPB - 1) / TPB;  // 32768
    rot3_kernel_v8<<<(int)blocks, TPB>>>(x, w, out);
}

// round 17
// speedup vs baseline: 1.0106x; 1.0106x over previous
#include <cuda_runtime.h>

// out[b,i,n] = sum_j w[i,j] * x[b,j,n]
// x: [256, 3, 65536] fp32, w: [3,3] fp32, out: [256, 3, 65536] fp32
//
// FINAL — converged at the chip's path-independent LTS/L2 fabric ceiling.
// 402.6 MB compulsory traffic per iteration / ~6.34 TB/s sustained =>
// ~63.5us replay period. 11 variants benched; all viable configs cluster
// at 63.5-64.3us (run-to-run noise +-0.5us on identical source).
//
// Best-measured configuration (R10, 63.52us):
//   - 1 float4 position per thread: 3x front-batched LDG.128 (MLP_p1=3)
//   - default-policy loads (beat .cs/.cg/evict_last in every test)
//   - write-through stores (__stwt)
//   - 16384 blocks x 256 threads
// Rejected by measurement: VPT=2 (~=), VPT=4 (-1%), L2 evict_last
// cross-replay residency x2 (~=), persistent grid-stride (-17%),
// TPB=128 (~=, slightly worse).

static constexpr int N_COLS   = 65536;
static constexpr int N4       = N_COLS / 4;        // 16384 float4 per row
static constexpr int BATCH    = 256;
static constexpr long TOTAL4  = (long)BATCH * N4;  // 4,194,304 threads

__global__ __launch_bounds__(256) void rot3_kernel_final(
    const float4* __restrict__ x,
    const float*  __restrict__ w,
    float4* __restrict__ out)
{
    long idx = (long)blockIdx.x * blockDim.x + threadIdx.x;
    if (idx >= TOTAL4) return;

    int b = (int)(idx >> 14);        // idx / N4
    int n = (int)(idx & (N4 - 1));   // idx % N4

    // Broadcast weight loads — L1-resident after first warp.
    float w00 = __ldg(w + 0), w01 = __ldg(w + 1), w02 = __ldg(w + 2);
    float w10 = __ldg(w + 3), w11 = __ldg(w + 4), w12 = __ldg(w + 5);
    float w20 = __ldg(w + 6), w21 = __ldg(w + 7), w22 = __ldg(w + 8);

    const float4* xb = x + (size_t)b * 3 * N4;
    float4 x0 = __ldg(xb + n);
    float4 x1 = __ldg(xb + N4 + n);
    float4 x2 = __ldg(xb + 2 * N4 + n);

    float4 o0, o1, o2;
    o0.x = w00 * x0.x + w01 * x1.x + w02 * x2.x;
    o0.y = w00 * x0.y + w01 * x1.y + w02 * x2.y;
    o0.z = w00 * x0.z + w01 * x1.z + w02 * x2.z;
    o0.w = w00 * x0.w + w01 * x1.w + w02 * x2.w;

    o1.x = w10 * x0.x + w11 * x1.x + w12 * x2.x;
    o1.y = w10 * x0.y + w11 * x1.y + w12 * x2.y;
    o1.z = w10 * x0.z + w11 * x1.z + w12 * x2.z;
    o1.w = w10 * x0.w + w11 * x1.w + w12 * x2.w;

    o2.x = w20 * x0.x + w21 * x1.x + w22 * x2.x;
    o2.y = w20 * x0.y + w21 * x1.y + w22 * x2.y;
    o2.z = w20 * x0.z + w21 * x1.z + w22 * x2.z;
    o2.w = w20 * x0.w + w21 * x1.w + w22 * x2.w;

    float4* ob = out + (size_t)b * 3 * N4;
    __stwt(ob + n,          o0);
    __stwt(ob + N4 + n,     o1);
    __stwt(ob + 2 * N4 + n, o2);
}

extern "C" void kernel_launch(void* const* d_in, const int* in_sizes, int n_in,
                              void* d_out, int out_size)
{
    const float4* x = (const float4*)d_in[0];
    const float*  w = (const float*)d_in[1];
    float4* out = (float4*)d_out;

    const int threads = 256;
    const long blocks = (TOTAL4 + threads - 1) / threads;  // 16384
    rot3_kernel_final<<<(int)blocks, threads>>>(x, w, out);
}